// round 3
// baseline (speedup 1.0000x reference)
#include <cuda_runtime.h>
#include <cstdint>

// Problem constants (fixed shapes):
//   B=128, T=2048, F_IN=32, R=256, H=256, F_OUT=32, future_n=64
//   total tokens N = 128 * (2048+64) = 270336
#define NTOTAL 270336
#define TTOT   2112
#define TIN    2048

// Fused weights:  M = W_ih @ enc_W  ->  gates[n] = x[n] @ M^T + fused_bias
// f-gate dropped (c0 == 0). Layouts are [k][hj] (k-major) for coalesced smem fill.
__device__ float g_Mi[32 * 256];
__device__ float g_Mg[32 * 256];
__device__ float g_Mo[32 * 256];
__device__ float g_bi[256];
__device__ float g_bg[256];
__device__ float g_bo[256];
// h scratch: [NTOTAL][256] fp32 (276.8 MB, static device array per harness rules)
__device__ float g_h[(size_t)NTOTAL * 256];

__device__ __forceinline__ float fast_sig(float v) {
    // 1/(1+e^-v); __expf(+inf)->inf, __fdividef(x, inf)->0  => correct saturation
    return __fdividef(1.0f, 1.0f + __expf(-v));
}
__device__ __forceinline__ float fast_tanh(float v) {
    // 1 - 2/(1+e^{2v}); saturates correctly at +/-1
    return 1.0f - __fdividef(2.0f, 1.0f + __expf(2.0f * v));
}

// ---------------------------------------------------------------------------
// K1: fold encoder into LSTM input weights.
//   Mi[k][hj] = sum_r W_ih[hj     ][r] * enc_W[r][k]
//   Mg[k][hj] = sum_r W_ih[512+hj][r] * enc_W[r][k]
//   Mo[k][hj] = sum_r W_ih[768+hj][r] * enc_W[r][k]
//   b*[hj]    = sum_r W_ih[row][r]*enc_b[r] + b_ih[row] + b_hh[row]
// ---------------------------------------------------------------------------
__global__ void prep_kernel(const float* __restrict__ Wih,
                            const float* __restrict__ encW,
                            const float* __restrict__ encb,
                            const float* __restrict__ bih,
                            const float* __restrict__ bhh) {
    int tid = blockIdx.x * blockDim.x + threadIdx.x;
    if (tid < 24576) {                       // 3 planes * 256 hj * 32 k
        int p   = tid >> 13;                 // plane: 0=i, 1=g, 2=o
        int rem = tid & 8191;
        int hj  = rem >> 5;
        int k   = rem & 31;
        int row = hj + (p == 0 ? 0 : (p == 1 ? 512 : 768));
        const float* wr = Wih + row * 256;
        float s = 0.0f;
        #pragma unroll 8
        for (int r = 0; r < 256; r++) s += wr[r] * encW[r * 32 + k];
        float* dst = (p == 0) ? g_Mi : (p == 1 ? g_Mg : g_Mo);
        dst[k * 256 + hj] = s;
    } else if (tid < 24576 + 768) {
        int q  = tid - 24576;
        int p  = q >> 8;
        int hj = q & 255;
        int row = hj + (p == 0 ? 0 : (p == 1 ? 512 : 768));
        const float* wr = Wih + row * 256;
        float s = 0.0f;
        #pragma unroll 8
        for (int r = 0; r < 256; r++) s += wr[r] * encb[r];
        s += bih[row] + bhh[row];
        float* dst = (p == 0) ? g_bi : (p == 1 ? g_bg : g_bo);
        dst[hj] = s;
    }
}

// ---------------------------------------------------------------------------
// K2: gates GEMM (K=32) + LSTM elementwise -> g_h.
// Grid: (4 hj-columns of 64, Y token-strips). Block = 256 threads.
// Block tile: 64 tokens x 64 hj; thread tile: 4 tok x 4 hj x 3 gates (48 accs).
// M slice (24 KB) loaded to smem once per block, reused over all token tiles.
// ---------------------------------------------------------------------------
__global__ __launch_bounds__(256, 2)
void gates_kernel(const float* __restrict__ x) {
    __shared__ __align__(16) float Mi_s[32 * 64];
    __shared__ __align__(16) float Mg_s[32 * 64];
    __shared__ __align__(16) float Mo_s[32 * 64];
    __shared__ float bi_s[64], bg_s[64], bo_s[64];
    __shared__ __align__(16) float X_s[64 * 36];   // [tok][32], pad 36 (align+banks)

    int tid   = threadIdx.x;
    int col   = blockIdx.x;       // hj column: 0..3
    int hbase = col * 64;

    for (int i = tid; i < 2048; i += 256) {
        int k = i >> 6, j = i & 63;
        Mi_s[i] = g_Mi[k * 256 + hbase + j];
        Mg_s[i] = g_Mg[k * 256 + hbase + j];
        Mo_s[i] = g_Mo[k * 256 + hbase + j];
    }
    if (tid < 64) {
        bi_s[tid] = g_bi[hbase + tid];
        bg_s[tid] = g_bg[hbase + tid];
        bo_s[tid] = g_bo[hbase + tid];
    }

    int hjg = tid & 15, tokg = tid >> 4;
    int hj0 = hjg * 4, tok0 = tokg * 4;

    for (int tile = blockIdx.y; tile < NTOTAL / 64; tile += gridDim.y) {
        int n0 = tile * 64;
        __syncthreads();
        {   // load X tile [64 tok][32] (t >= 2048 clamps to last input step)
            int tk = tid >> 2, seg = tid & 3;
            int n = n0 + tk;
            int b = n / TTOT;
            int t = n - b * TTOT;
            if (t > TIN - 1) t = TIN - 1;
            const float* src = x + (size_t)(b * TIN + t) * 32 + seg * 8;
            float4 a0 = *(const float4*)src;
            float4 a1 = *(const float4*)(src + 4);
            *(float4*)&X_s[tk * 36 + seg * 8]     = a0;
            *(float4*)&X_s[tk * 36 + seg * 8 + 4] = a1;
        }
        __syncthreads();

        float ai[16], ag[16], ao[16];
        #pragma unroll
        for (int q = 0; q < 16; q++) { ai[q] = 0.f; ag[q] = 0.f; ao[q] = 0.f; }

        #pragma unroll
        for (int k4 = 0; k4 < 32; k4 += 4) {
            float4 xv[4];
            #pragma unroll
            for (int j = 0; j < 4; j++)
                xv[j] = *(const float4*)&X_s[(tok0 + j) * 36 + k4];
            #pragma unroll
            for (int kk = 0; kk < 4; kk++) {
                float4 mi = *(const float4*)&Mi_s[(k4 + kk) * 64 + hj0];
                float4 mg = *(const float4*)&Mg_s[(k4 + kk) * 64 + hj0];
                float4 mo = *(const float4*)&Mo_s[(k4 + kk) * 64 + hj0];
                #pragma unroll
                for (int j = 0; j < 4; j++) {
                    float xs = ((const float*)&xv[j])[kk];
                    ai[j*4+0] += xs * mi.x; ai[j*4+1] += xs * mi.y;
                    ai[j*4+2] += xs * mi.z; ai[j*4+3] += xs * mi.w;
                    ag[j*4+0] += xs * mg.x; ag[j*4+1] += xs * mg.y;
                    ag[j*4+2] += xs * mg.z; ag[j*4+3] += xs * mg.w;
                    ao[j*4+0] += xs * mo.x; ao[j*4+1] += xs * mo.y;
                    ao[j*4+2] += xs * mo.z; ao[j*4+3] += xs * mo.w;
                }
            }
        }

        // LSTM elementwise (c0=0): h = sig(o) * tanh(sig(i) * tanh(g))
        #pragma unroll
        for (int j = 0; j < 4; j++) {
            size_t n = (size_t)(n0 + tok0 + j);
            float4 hv;
            float* hp = (float*)&hv;
            #pragma unroll
            for (int q = 0; q < 4; q++) {
                float iv = ai[j*4+q] + bi_s[hj0 + q];
                float gv = ag[j*4+q] + bg_s[hj0 + q];
                float ov = ao[j*4+q] + bo_s[hj0 + q];
                float cc = fast_sig(iv) * fast_tanh(gv);
                hp[q] = fast_sig(ov) * fast_tanh(cc);
            }
            *(float4*)&g_h[n * 256 + hbase + hj0] = hv;
        }
    }
}

// ---------------------------------------------------------------------------
// K3: decoder GEMM  out[n][o] = sum_k dec_W[o][k] * h[n][k] + dec_b[o]
// Block tile: 96 tokens x 32 outs; thread tile: 6 tok x 2 o; k chunked by 32.
// dec_W held in smem (padded rows), h chunk streamed through smem.
// ---------------------------------------------------------------------------
#define TOK3 96
__global__ __launch_bounds__(256, 3)
void dec_kernel(const float* __restrict__ decW,
                const float* __restrict__ decb,
                float* __restrict__ out) {
    __shared__ __align__(16) float w_s[32 * 260];   // [o][256] pad 260
    __shared__ __align__(16) float h_s[TOK3 * 36];  // [tok][32] pad 36
    int tid = threadIdx.x;

    for (int i = tid; i < 8192; i += 256) {
        int o = i >> 8, k = i & 255;
        w_s[o * 260 + k] = decW[i];
    }
    int og = tid & 15, tg = tid >> 4;  // 16 o-pairs x 16 token-slots
    int o0 = og * 2;
    float db0 = decb[o0], db1 = decb[o0 + 1];

    const int NT3 = NTOTAL / TOK3;     // 2816 tiles
    for (int tile = blockIdx.x; tile < NT3; tile += gridDim.x) {
        int n0 = tile * TOK3;
        float acc0[6], acc1[6];
        #pragma unroll
        for (int m = 0; m < 6; m++) { acc0[m] = 0.f; acc1[m] = 0.f; }

        for (int c = 0; c < 8; c++) {
            __syncthreads();
            #pragma unroll
            for (int i = tid; i < 768; i += 256) {       // 96 tok x 32 k / 4
                int tok = i >> 3, seg = i & 7;
                *(float4*)&h_s[tok * 36 + seg * 4] =
                    *(const float4*)&g_h[(size_t)(n0 + tok) * 256 + c * 32 + seg * 4];
            }
            __syncthreads();
            const float* wr0 = &w_s[o0 * 260 + c * 32];
            const float* wr1 = wr0 + 260;
            #pragma unroll
            for (int kk = 0; kk < 32; kk += 4) {
                float4 w0 = *(const float4*)(wr0 + kk);
                float4 w1 = *(const float4*)(wr1 + kk);
                #pragma unroll
                for (int m = 0; m < 6; m++) {
                    float4 hv = *(const float4*)&h_s[(tg + 16 * m) * 36 + kk];
                    acc0[m] += hv.x * w0.x + hv.y * w0.y + hv.z * w0.z + hv.w * w0.w;
                    acc1[m] += hv.x * w1.x + hv.y * w1.y + hv.z * w1.z + hv.w * w1.w;
                }
            }
        }
        #pragma unroll
        for (int m = 0; m < 6; m++) {
            int n = n0 + tg + 16 * m;
            float2 r;
            r.x = acc0[m] + db0;
            r.y = acc1[m] + db1;
            *(float2*)&out[(size_t)n * 32 + o0] = r;
        }
    }
}

// ---------------------------------------------------------------------------
// Inputs (metadata order): input_seq, enc_W, enc_b, W_ih, W_hh, b_ih, b_hh,
//                          dec_W, dec_b, future_n
// W_hh is dead (state never updates from zeros); future_n fixed at 64.
// ---------------------------------------------------------------------------
extern "C" void kernel_launch(void* const* d_in, const int* in_sizes, int n_in,
                              void* d_out, int out_size) {
    (void)in_sizes; (void)n_in; (void)out_size;
    const float* input = (const float*)d_in[0];
    const float* encW  = (const float*)d_in[1];
    const float* encb  = (const float*)d_in[2];
    const float* Wih   = (const float*)d_in[3];
    const float* bih   = (const float*)d_in[5];
    const float* bhh   = (const float*)d_in[6];
    const float* decW  = (const float*)d_in[7];
    const float* decb  = (const float*)d_in[8];
    float* out = (float*)d_out;

    prep_kernel<<<99, 256>>>(Wih, encW, encb, bih, bhh);
    dim3 g2(4, 74);
    gates_kernel<<<g2, 256>>>(input);
    dec_kernel<<<444, 256>>>(decW, decb, out);
}